// round 16
// baseline (speedup 1.0000x reference)
#include <cuda_runtime.h>
#include <cuda_fp16.h>
#include <math.h>
#include <stdint.h>

// Problem constants
#define Bb   4
#define Cc   64
#define Hh   96
#define Ww   96
#define HW   (Hh*Ww)            // 9216
#define Oo   64
#define CIN3 (3*Cc)             // 192
#define IMG  (Cc*HW)            // 589824
#define NPIX (Bb*HW)            // 36864
#define NCH  27                 // K chunks of 64: K = k*192 + c (k-major)
#define NPAIR (Bb * 96 * HW)    // 3538944 uints (channel-pair words)
#define UPAD 128                // pad (uints) each side

// Scratch
__device__ float4 g_mw[Bb * 9 * HW];
__device__ int    g_me[Bb * 9 * HW];
__device__ __align__(16) uint32_t g_xp_raw[NPAIR + 2 * UPAD];   // pair-interleaved fp16
__device__ __align__(16) uint32_t g_xsp_raw[NPAIR + 2 * UPAD];  // shifted by 1 pixel
__device__ __half g_wh[NCH * 64 * 64];

// ---------------- helpers ----------------
__device__ __forceinline__ uint32_t smem_to_u32(const void* p) {
    uint32_t a;
    asm("{ .reg .u64 t; cvta.to.shared.u64 t, %1; cvt.u32.u64 %0, t; }"
        : "=r"(a) : "l"(p));
    return a;
}
__device__ __forceinline__ void ldsm_x4(uint32_t* r, uint32_t addr) {
    asm volatile("ldmatrix.sync.aligned.m8n8.x4.shared.b16 {%0,%1,%2,%3}, [%4];"
        : "=r"(r[0]), "=r"(r[1]), "=r"(r[2]), "=r"(r[3]) : "r"(addr));
}
__device__ __forceinline__ void mma_f16(float* d, const uint32_t* a,
                                        uint32_t b0, uint32_t b1) {
    asm volatile("mma.sync.aligned.m16n8k16.row.col.f32.f16.f16.f32 "
        "{%0,%1,%2,%3}, {%4,%5,%6,%7}, {%8,%9}, {%0,%1,%2,%3};"
        : "+f"(d[0]), "+f"(d[1]), "+f"(d[2]), "+f"(d[3])
        : "r"(a[0]), "r"(a[1]), "r"(a[2]), "r"(a[3]), "r"(b0), "r"(b1));
}
__device__ __forceinline__ void cp_async16(uint32_t smem_addr, const void* gptr) {
    asm volatile("cp.async.cg.shared.global [%0], [%1], 16;"
        :: "r"(smem_addr), "l"(gptr));
}
#define CP_COMMIT() asm volatile("cp.async.commit_group;" ::: "memory")
#define CP_WAIT0()  asm volatile("cp.async.wait_group 0;" ::: "memory")

// packed f32x2 FMA (IEEE fp32 per lane)
__device__ __forceinline__ void ffma2(unsigned long long& c,
                                      unsigned long long a,
                                      unsigned long long b) {
    asm("fma.rn.f32x2 %0, %1, %2, %0;" : "+l"(c) : "l"(a), "l"(b));
}
__device__ __forceinline__ unsigned long long dup2(float x) {
    unsigned long long d;
    asm("mov.b64 %0, {%1, %1};" : "=l"(d) : "r"(__float_as_uint(x)));
    return d;
}
__device__ __forceinline__ void unpk2(float& lo, float& hi, unsigned long long v) {
    unsigned int l, h;
    asm("mov.b64 {%0, %1}, %2;" : "=r"(l), "=r"(h) : "l"(v));
    lo = __uint_as_float(l); hi = __uint_as_float(h);
}

// ---------------------------------------------------------------------------
// Kernel 1: prep (block-range dispatch, no smem):
//   [0, 13824):      diff + pair-interleaved fp16 repack (+ shifted copy)
//   [13824, 14256):  weight prep -> fp16 B tiles, XOR-swizzled
// ---------------------------------------------------------------------------
#define RPB (NPAIR / 256)       // 13824
__global__ void prep_kernel(const float* __restrict__ ref,
                            const float* __restrict__ dist,
                            const float* __restrict__ dw,
                            float* __restrict__ out_diff,
                            uint32_t* __restrict__ xp,    // +UPAD base
                            uint32_t* __restrict__ xsp,   // +UPAD base
                            __half* __restrict__ wh) {
    int tid = threadIdx.x;
    int bid = blockIdx.x;
    if (bid >= RPB) {
        int i = (bid - RPB) * 256 + tid;
        int c  = i & 63;
        int o  = (i >> 6) & 63;
        int ch = i >> 12;
        int k  = ch / 3;
        int cg = (ch % 3) * 64 + c;
        float v = __ldg(dw + o * (CIN3 * 9) + cg * 9 + k);
        int elem = o * 64 + (((c >> 3) ^ (o & 7)) << 3) + (c & 7);
        wh[ch * 4096 + elem] = __float2half_rn(v);
        return;
    }
    int i = bid * 256 + tid;                 // pair-word index
    int b  = i / (96 * HW);
    int r  = i - b * (96 * HW);
    int c2 = r / HW;
    int e  = r - c2 * HW;
    int c0 = 2 * c2;
    float v0, v1;
    if (c0 < Cc) {
        v0 = __ldg(ref + (b * Cc + c0)     * HW + e);
        v1 = __ldg(ref + (b * Cc + c0 + 1) * HW + e);
    } else if (c0 < 2 * Cc) {
        v0 = __ldg(dist + (b * Cc + (c0 - Cc))     * HW + e);
        v1 = __ldg(dist + (b * Cc + (c0 - Cc) + 1) * HW + e);
    } else {
        int cc = c0 - 2 * Cc;
        float r0 = __ldg(ref  + (b * Cc + cc) * HW + e);
        float d0 = __ldg(dist + (b * Cc + cc) * HW + e);
        float r1 = __ldg(ref  + (b * Cc + cc + 1) * HW + e);
        float d1 = __ldg(dist + (b * Cc + cc + 1) * HW + e);
        v0 = (r0 - d0) * (r0 - d0);
        v1 = (r1 - d1) * (r1 - d1);
        out_diff[(b * Cc + cc) * HW + e]     = v0;
        out_diff[(b * Cc + cc + 1) * HW + e] = v1;
    }
    __half2 h2 = __float22half2_rn(make_float2(v0, v1));
    uint32_t un = *(uint32_t*)&h2;
    xp[i]      = un;
    xsp[i - 1] = un;    // pad covers i=0
}

// ---------------------------------------------------------------------------
// Kernel 2: offset conv3x3 + bilinear meta (R15 version, unchanged).
// 288 blocks x 256 thr; 2 threads/pixel split channels; f32x2 FMA.
// dyn smem: s_w 46080 B | s_red 9216 B = 55296 B
// ---------------------------------------------------------------------------
__global__ __launch_bounds__(256) void offset_meta_kernel(
        const float* __restrict__ ref,
        const float* __restrict__ ow, const float* __restrict__ ob,
        float4* __restrict__ mw, int* __restrict__ me) {
    extern __shared__ __align__(16) float smem_f[];
    float*  s_w   = smem_f;
    float2* s_red = (float2*)(smem_f + 576 * 20);

    int tid = threadIdx.x;
    for (int i = tid; i < 18 * 576; i += 256) {
        int o = i / 576, ck = i % 576;
        s_w[ck * 20 + o] = ow[i];
    }
    __syncthreads();

    int lp   = tid & 127;
    int half = tid >> 7;
    int p = blockIdx.x * 128 + lp;
    int b = p / HW;
    int pix = p % HW;
    int y = pix / Ww, x = pix % Ww;

    int  idx9[9]; bool ok9[9];
#pragma unroll
    for (int ky = 0; ky < 3; ky++)
#pragma unroll
        for (int kx = 0; kx < 3; kx++) {
            int yt = y + ky - 1, xt = x + kx - 1;
            bool ok = (yt >= 0) && (yt < Hh) && (xt >= 0) && (xt < Ww);
            ok9[ky * 3 + kx] = ok;
            idx9[ky * 3 + kx] = (ok ? yt : 0) * Ww + (ok ? xt : 0);
        }

    unsigned long long acc[9];
#pragma unroll
    for (int j = 0; j < 9; j++) acc[j] = 0ull;

    const float* xb = ref + b * IMG + half * 32 * HW;
    for (int cj = 0; cj < 32; cj++) {
        int c = half * 32 + cj;
        const float* xc = xb + cj * HW;
#pragma unroll
        for (int k = 0; k < 9; k++) {
            float v = ok9[k] ? __ldg(xc + idx9[k]) : 0.f;
            unsigned long long d = dup2(v);
            const unsigned long long* wp =
                (const unsigned long long*)&s_w[(c * 9 + k) * 20];
            ffma2(acc[0], d, wp[0]);
            ffma2(acc[1], d, wp[1]);
            ffma2(acc[2], d, wp[2]);
            ffma2(acc[3], d, wp[3]);
            ffma2(acc[4], d, wp[4]);
            ffma2(acc[5], d, wp[5]);
            ffma2(acc[6], d, wp[6]);
            ffma2(acc[7], d, wp[7]);
            ffma2(acc[8], d, wp[8]);
        }
    }

    if (half == 1) {
#pragma unroll
        for (int j = 0; j < 9; j++) {
            float lo, hi; unpk2(lo, hi, acc[j]);
            s_red[lp * 9 + j] = make_float2(lo, hi);
        }
    }
    __syncthreads();
    if (half == 0) {
#pragma unroll
        for (int k = 0; k < 9; k++) {
            float offy, offx;
            unpk2(offy, offx, acc[k]);
            float2 r2 = s_red[lp * 9 + k];
            offy += r2.x + __ldg(ob + 2 * k);
            offx += r2.y + __ldg(ob + 2 * k + 1);
            float py = (float)(y - 1 + k / 3) + offy;
            float px = (float)(x - 1 + k % 3) + offx;
            float fy = floorf(py), fx = floorf(px);
            int y0 = (int)fy, x0 = (int)fx;
            float dy = py - fy, dx = px - fx;
            float wv[4];
#pragma unroll
            for (int t = 0; t < 4; t++) {
                int yt = y0 + (t >> 1);
                int xt = x0 + (t & 1);
                float wt = ((t >> 1) ? dy : (1.f - dy)) * ((t & 1) ? dx : (1.f - dx));
                bool valid = (yt >= 0) && (yt < Hh) && (xt >= 0) && (xt < Ww);
                wv[t] = valid ? wt : 0.f;
            }
            int y0c = y0 < -1 ? -1 : (y0 > Hh ? Hh : y0);
            int x0c = x0 < -1 ? -1 : (x0 > Ww ? Ww : x0);
            int e0 = y0c * Ww + x0c;
            int mo = (b * 9 + k) * HW + pix;
            mw[mo] = make_float4(wv[0], wv[1], wv[2], wv[3]);
            me[mo] = e0;
        }
    }
}

// ---------------------------------------------------------------------------
// Kernel 3: deformable conv (R10 tile config; pair-interleaved gather:
// 2x LDG.64 per channel-pair covers both x-taps of 2 channels).
// Per buffer (24KB): A@0 16K | B@16K 8K
// ---------------------------------------------------------------------------
#define SM_BUF   24576
#define SM_AHOF  0
#define SM_BHOF  16384
#define SM_TOTAL (2 * SM_BUF)

__global__ __launch_bounds__(256, 2) void deform_kernel(
        const uint32_t* __restrict__ xp, const uint32_t* __restrict__ xsp,
        const float4* __restrict__ mw, const int* __restrict__ me,
        const __half* __restrict__ wh,
        const float* __restrict__ db, float* __restrict__ out) {
    extern __shared__ char smem[];
    uint32_t sb = smem_to_u32(smem);

    int tid  = threadIdx.x;
    int lane = tid & 31;
    int warp = tid >> 5;
    int b    = blockIdx.x / 72;
    int pix0 = (blockIdx.x % 72) * 128;

    int p  = tid & 127;
    int cq = tid >> 7;               // channel half (32 ch = 16 pairs)
    uint32_t a_sts = (uint32_t)p * 128;

    int m0 = (warp & 3) * 32;
    int n0 = (warp >> 2) * 32;

    float acc[2][4][4];
#pragma unroll
    for (int i = 0; i < 2; i++)
#pragma unroll
        for (int j = 0; j < 4; j++)
#pragma unroll
            for (int q = 0; q < 4; q++) acc[i][j][q] = 0.f;

    uint32_t a_m  = lane & 15;
    uint32_t a_kc = lane >> 4;
    uint32_t b_n  = ((lane >> 4) << 3) + (lane & 7);
    uint32_t b_kc = (lane >> 3) & 1;

    int bcp0 = tid;

    // build quarter q: channel-pairs q*4 .. q*4+3 (8 channels)
    auto build_q = [&](int ch, int q, const __half2* w4, const uint2* srcp) {
        char* bufc = smem + (ch & 1) * SM_BUF;
        uint32_t hp[4];
#pragma unroll
        for (int jj = 0; jj < 4; jj++) {
            int j = q * 4 + jj;
            uint2 t  = __ldg(srcp + j * (HW / 2));
            uint2 bo = __ldg(srcp + j * (HW / 2) + (Ww / 2));
            __half2 a0 = *(__half2*)&t.x,  a1 = *(__half2*)&t.y;
            __half2 b0 = *(__half2*)&bo.x, b1 = *(__half2*)&bo.y;
            __half2 v = __hfma2(w4[3], b1,
                        __hfma2(w4[2], b0,
                        __hfma2(w4[1], a1, __hmul2(w4[0], a0))));
            hp[jj] = *(uint32_t*)&v;
        }
        int kc = cq * 4 + q;
        uint32_t off = a_sts + (uint32_t)((kc ^ (p & 7)) << 4);
        *(uint4*)(bufc + SM_AHOF + off) = make_uint4(hp[0], hp[1], hp[2], hp[3]);
    };

    auto chunk_meta = [&](int ch, __half2* w4, const uint2*& srcp) {
        int k   = ch / 3;
        int cbl = ch - 3 * k;
        float4 w = __ldg(mw + (b * 9 + k) * HW + pix0 + p);
        int   e0 = __ldg(me + (b * 9 + k) * HW + pix0 + p);
        w4[0] = __float2half2_rn(w.x);
        w4[1] = __float2half2_rn(w.y);
        w4[2] = __float2half2_rn(w.z);
        w4[3] = __float2half2_rn(w.w);
        int sel = e0 & 1;
        int plane0 = b * 96 + cbl * 32 + cq * 16;
        const uint32_t* base = sel ? xsp : xp;
        srcp = (const uint2*)base + ((plane0 * HW + e0 - sel) >> 1);
    };

    auto stage_B = [&](int ch) {
        uint32_t bufb = sb + (ch & 1) * SM_BUF;
        const char* gh = (const char*)(wh + ch * 4096);
        cp_async16(bufb + SM_BHOF + bcp0 * 16, gh + bcp0 * 16);
        cp_async16(bufb + SM_BHOF + (bcp0 + 256) * 16, gh + (bcp0 + 256) * 16);
        CP_COMMIT();
    };

    // prologue: chunk 0
    stage_B(0);
    {
        __half2 w4[4]; const uint2* srcp;
        chunk_meta(0, w4, srcp);
#pragma unroll
        for (int q = 0; q < 4; q++) build_q(0, q, w4, srcp);
    }
    CP_WAIT0();
    __syncthreads();

    for (int ch = 0; ch < NCH; ch++) {
        int nxt = ch + 1;
        bool has_nxt = (nxt < NCH);
        if (has_nxt) stage_B(nxt);

        __half2 nw4[4];
        const uint2* nsrc = (const uint2*)xp;
        if (has_nxt) chunk_meta(nxt, nw4, nsrc);

        uint32_t bufb = sb + (ch & 1) * SM_BUF;
#pragma unroll
        for (int ks = 0; ks < 4; ks++) {
            uint32_t ah[2][4], bh[2][4];
#pragma unroll
            for (int mi_ = 0; mi_ < 2; mi_++) {
                uint32_t row = m0 + mi_ * 16 + a_m;
                uint32_t aoff = row * 128 + ((((ks << 1) + a_kc) ^ (row & 7)) << 4);
                ldsm_x4(ah[mi_], bufb + SM_AHOF + aoff);
            }
#pragma unroll
            for (int g = 0; g < 2; g++) {
                uint32_t n  = n0 + g * 16 + b_n;
                uint32_t kc = (ks << 1) + b_kc;
                uint32_t boff = n * 128 + ((kc ^ (n & 7)) << 4);
                ldsm_x4(bh[g], bufb + SM_BHOF + boff);
            }
#pragma unroll
            for (int mi_ = 0; mi_ < 2; mi_++)
#pragma unroll
                for (int g = 0; g < 2; g++)
#pragma unroll
                    for (int s2 = 0; s2 < 2; s2++) {
                        int ni = g * 2 + s2;
                        mma_f16(acc[mi_][ni], ah[mi_], bh[g][2 * s2], bh[g][2 * s2 + 1]);
                    }
            if (has_nxt) build_q(nxt, ks, nw4, nsrc);
        }

        CP_WAIT0();
        __syncthreads();
    }

    // epilogue: bias + relu
    int r  = lane >> 2;
    int cp = (lane & 3) * 2;
#pragma unroll
    for (int mi_ = 0; mi_ < 2; mi_++) {
        int pixb = pix0 + m0 + mi_ * 16 + r;
#pragma unroll
        for (int ni = 0; ni < 4; ni++) {
            int o = n0 + ni * 8 + cp;
            float b0v = __ldg(db + o);
            float b1v = __ldg(db + o + 1);
            float* o0 = out + (size_t)(b * Oo + o) * HW;
            float* o1 = out + (size_t)(b * Oo + o + 1) * HW;
            float v;
            v = acc[mi_][ni][0] + b0v; o0[pixb]     = v > 0.f ? v : 0.f;
            v = acc[mi_][ni][1] + b1v; o1[pixb]     = v > 0.f ? v : 0.f;
            v = acc[mi_][ni][2] + b0v; o0[pixb + 8] = v > 0.f ? v : 0.f;
            v = acc[mi_][ni][3] + b1v; o1[pixb + 8] = v > 0.f ? v : 0.f;
        }
    }
}

// ---------------------------------------------------------------------------
extern "C" void kernel_launch(void* const* d_in, const int* in_sizes, int n_in,
                              void* d_out, int out_size) {
    const float* ref  = (const float*)d_in[0];
    const float* dist = (const float*)d_in[1];
    const float* ow   = (const float*)d_in[2];
    const float* ob   = (const float*)d_in[3];
    const float* dw   = (const float*)d_in[4];
    const float* db   = (const float*)d_in[5];
    float* out = (float*)d_out;
    float* out_feat = out;
    float* out_diff = out + Bb * IMG;

    float4*   mw;  cudaGetSymbolAddress((void**)&mw, g_mw);
    int*      me;  cudaGetSymbolAddress((void**)&me, g_me);
    uint32_t* xpr; cudaGetSymbolAddress((void**)&xpr, g_xp_raw);
    uint32_t* xsr; cudaGetSymbolAddress((void**)&xsr, g_xsp_raw);
    __half*   wh;  cudaGetSymbolAddress((void**)&wh, g_wh);
    uint32_t* xp  = xpr + UPAD;
    uint32_t* xsp = xsr + UPAD;

    cudaFuncSetAttribute(deform_kernel,
                         cudaFuncAttributeMaxDynamicSharedMemorySize, SM_TOTAL);
    cudaFuncSetAttribute(offset_meta_kernel,
                         cudaFuncAttributeMaxDynamicSharedMemorySize, 55296);

    prep_kernel<<<RPB + 432, 256>>>(ref, dist, dw, out_diff, xp, xsp, wh);
    offset_meta_kernel<<<288, 256, 55296>>>(ref, ow, ob, mw, me);
    deform_kernel<<<NPIX / 128, 256, SM_TOTAL>>>(xp, xsp, mw, me, wh, db, out_feat);
}

// round 17
// speedup vs baseline: 1.0804x; 1.0804x over previous
#include <cuda_runtime.h>
#include <cuda_fp16.h>
#include <math.h>
#include <stdint.h>

// Problem constants
#define Bb   4
#define Cc   64
#define Hh   96
#define Ww   96
#define HW   (Hh*Ww)            // 9216
#define Oo   64
#define CIN3 (3*Cc)             // 192
#define IMG  (Cc*HW)            // 589824
#define NPIX (Bb*HW)            // 36864
#define NCH  27                 // K chunks of 64: K = k*192 + c (k-major)
#define NTOT (Bb*CIN3*HW)       // 7077888
#define XPAD 256

// Scratch
__device__ float4 g_mw[Bb * 9 * HW];
__device__ int    g_me[Bb * 9 * HW];
__device__ __half g_xn_raw[NTOT + 2 * XPAD];
__device__ __half g_xs_raw[NTOT + 2 * XPAD];
__device__ __half g_wh[NCH * 64 * 64];

// ---------------- helpers ----------------
__device__ __forceinline__ uint32_t smem_to_u32(const void* p) {
    uint32_t a;
    asm("{ .reg .u64 t; cvta.to.shared.u64 t, %1; cvt.u32.u64 %0, t; }"
        : "=r"(a) : "l"(p));
    return a;
}
__device__ __forceinline__ void ldsm_x4(uint32_t* r, uint32_t addr) {
    asm volatile("ldmatrix.sync.aligned.m8n8.x4.shared.b16 {%0,%1,%2,%3}, [%4];"
        : "=r"(r[0]), "=r"(r[1]), "=r"(r[2]), "=r"(r[3]) : "r"(addr));
}
__device__ __forceinline__ void mma_f16(float* d, const uint32_t* a,
                                        uint32_t b0, uint32_t b1) {
    asm volatile("mma.sync.aligned.m16n8k16.row.col.f32.f16.f16.f32 "
        "{%0,%1,%2,%3}, {%4,%5,%6,%7}, {%8,%9}, {%0,%1,%2,%3};"
        : "+f"(d[0]), "+f"(d[1]), "+f"(d[2]), "+f"(d[3])
        : "r"(a[0]), "r"(a[1]), "r"(a[2]), "r"(a[3]), "r"(b0), "r"(b1));
}
__device__ __forceinline__ void cp_async16(uint32_t smem_addr, const void* gptr) {
    asm volatile("cp.async.cg.shared.global [%0], [%1], 16;"
        :: "r"(smem_addr), "l"(gptr));
}
#define CP_COMMIT() asm volatile("cp.async.commit_group;" ::: "memory")
#define CP_WAIT0()  asm volatile("cp.async.wait_group 0;" ::: "memory")

// packed f32x2 FMA (IEEE fp32 per lane)
__device__ __forceinline__ void ffma2(unsigned long long& c,
                                      unsigned long long a,
                                      unsigned long long b) {
    asm("fma.rn.f32x2 %0, %1, %2, %0;" : "+l"(c) : "l"(a), "l"(b));
}
__device__ __forceinline__ unsigned long long dup2(float x) {
    unsigned long long d;
    asm("mov.b64 %0, {%1, %1};" : "=l"(d) : "r"(__float_as_uint(x)));
    return d;
}
__device__ __forceinline__ void unpk2(float& lo, float& hi, unsigned long long v) {
    unsigned int l, h;
    asm("mov.b64 {%0, %1}, %2;" : "=r"(l), "=r"(h) : "l"(v));
    lo = __uint_as_float(l); hi = __uint_as_float(h);
}

// ---------------------------------------------------------------------------
// Kernel 1: prep (block-range dispatch, NO smem):
//   [0, 13824):      diff + fp16 NCHW repack (half2, + shifted copy)
//   [13824, 14256):  weight prep -> fp16 B tiles, XOR-swizzled
// ---------------------------------------------------------------------------
#define RPB (NTOT / 512)        // 13824 blocks, 2 elems/thread
__global__ void prep_kernel(const float* __restrict__ ref,
                            const float* __restrict__ dist,
                            const float* __restrict__ dw,
                            float* __restrict__ out_diff,
                            __half* __restrict__ xn,
                            __half* __restrict__ xs,
                            __half* __restrict__ wh) {
    int tid = threadIdx.x;
    int bid = blockIdx.x;
    if (bid >= RPB) {
        int i = (bid - RPB) * 256 + tid;
        int c  = i & 63;
        int o  = (i >> 6) & 63;
        int ch = i >> 12;
        int k  = ch / 3;
        int cg = (ch % 3) * 64 + c;
        float v = __ldg(dw + o * (CIN3 * 9) + cg * 9 + k);
        int elem = o * 64 + (((c >> 3) ^ (o & 7)) << 3) + (c & 7);
        wh[ch * 4096 + elem] = __float2half_rn(v);
        return;
    }
    int i2 = bid * 256 + tid;
    int i = i2 * 2;
    int b = i / (CIN3 * HW);
    int r = i - b * (CIN3 * HW);
    int c = r / HW;
    int e = r - c * HW;     // even; e+1 in same plane (HW even)
    float2 v2;
    if (c < Cc) {
        v2 = __ldg((const float2*)(ref + (b * Cc + c) * HW + e));
    } else if (c < 2 * Cc) {
        v2 = __ldg((const float2*)(dist + (b * Cc + (c - Cc)) * HW + e));
    } else {
        int cc = c - 2 * Cc;
        float2 rr = __ldg((const float2*)(ref  + (b * Cc + cc) * HW + e));
        float2 dd = __ldg((const float2*)(dist + (b * Cc + cc) * HW + e));
        v2.x = (rr.x - dd.x) * (rr.x - dd.x);
        v2.y = (rr.y - dd.y) * (rr.y - dd.y);
        *(float2*)(out_diff + (b * Cc + cc) * HW + e) = v2;
    }
    __half2 h2 = __float22half2_rn(v2);
    *((__half2*)xn + i2) = h2;
    if (i > 0) xs[i - 1] = __low2half(h2);
    xs[i] = __high2half(h2);
}

// ---------------------------------------------------------------------------
// Kernel 2: offset conv3x3 + bilinear meta (R15, unchanged).
// 288 blocks x 256 thr; 2 threads/pixel split channels; f32x2 FMA.
// dyn smem: s_w 46080 B | s_red 9216 B = 55296 B
// ---------------------------------------------------------------------------
__global__ __launch_bounds__(256) void offset_meta_kernel(
        const float* __restrict__ ref,
        const float* __restrict__ ow, const float* __restrict__ ob,
        float4* __restrict__ mw, int* __restrict__ me) {
    extern __shared__ __align__(16) float smem_f[];
    float*  s_w   = smem_f;
    float2* s_red = (float2*)(smem_f + 576 * 20);

    int tid = threadIdx.x;
    for (int i = tid; i < 18 * 576; i += 256) {
        int o = i / 576, ck = i % 576;
        s_w[ck * 20 + o] = ow[i];
    }
    __syncthreads();

    int lp   = tid & 127;
    int half = tid >> 7;
    int p = blockIdx.x * 128 + lp;
    int b = p / HW;
    int pix = p % HW;
    int y = pix / Ww, x = pix % Ww;

    int  idx9[9]; bool ok9[9];
#pragma unroll
    for (int ky = 0; ky < 3; ky++)
#pragma unroll
        for (int kx = 0; kx < 3; kx++) {
            int yt = y + ky - 1, xt = x + kx - 1;
            bool ok = (yt >= 0) && (yt < Hh) && (xt >= 0) && (xt < Ww);
            ok9[ky * 3 + kx] = ok;
            idx9[ky * 3 + kx] = (ok ? yt : 0) * Ww + (ok ? xt : 0);
        }

    unsigned long long acc[9];
#pragma unroll
    for (int j = 0; j < 9; j++) acc[j] = 0ull;

    const float* xb = ref + b * IMG + half * 32 * HW;
    for (int cj = 0; cj < 32; cj++) {
        int c = half * 32 + cj;
        const float* xc = xb + cj * HW;
#pragma unroll
        for (int k = 0; k < 9; k++) {
            float v = ok9[k] ? __ldg(xc + idx9[k]) : 0.f;
            unsigned long long d = dup2(v);
            const unsigned long long* wp =
                (const unsigned long long*)&s_w[(c * 9 + k) * 20];
            ffma2(acc[0], d, wp[0]);
            ffma2(acc[1], d, wp[1]);
            ffma2(acc[2], d, wp[2]);
            ffma2(acc[3], d, wp[3]);
            ffma2(acc[4], d, wp[4]);
            ffma2(acc[5], d, wp[5]);
            ffma2(acc[6], d, wp[6]);
            ffma2(acc[7], d, wp[7]);
            ffma2(acc[8], d, wp[8]);
        }
    }

    if (half == 1) {
#pragma unroll
        for (int j = 0; j < 9; j++) {
            float lo, hi; unpk2(lo, hi, acc[j]);
            s_red[lp * 9 + j] = make_float2(lo, hi);
        }
    }
    __syncthreads();
    if (half == 0) {
#pragma unroll
        for (int k = 0; k < 9; k++) {
            float offy, offx;
            unpk2(offy, offx, acc[k]);
            float2 r2 = s_red[lp * 9 + k];
            offy += r2.x + __ldg(ob + 2 * k);
            offx += r2.y + __ldg(ob + 2 * k + 1);
            float py = (float)(y - 1 + k / 3) + offy;
            float px = (float)(x - 1 + k % 3) + offx;
            float fy = floorf(py), fx = floorf(px);
            int y0 = (int)fy, x0 = (int)fx;
            float dy = py - fy, dx = px - fx;
            float wv[4];
#pragma unroll
            for (int t = 0; t < 4; t++) {
                int yt = y0 + (t >> 1);
                int xt = x0 + (t & 1);
                float wt = ((t >> 1) ? dy : (1.f - dy)) * ((t & 1) ? dx : (1.f - dx));
                bool valid = (yt >= 0) && (yt < Hh) && (xt >= 0) && (xt < Ww);
                wv[t] = valid ? wt : 0.f;
            }
            int y0c = y0 < -1 ? -1 : (y0 > Hh ? Hh : y0);
            int x0c = x0 < -1 ? -1 : (x0 > Ww ? Ww : x0);
            int e0 = y0c * Ww + x0c;
            int mo = (b * 9 + k) * HW + pix;
            mw[mo] = make_float4(wv[0], wv[1], wv[2], wv[3]);
            me[mo] = e0;
        }
    }
}

// ---------------------------------------------------------------------------
// Kernel 3: deformable conv (R10/R15 config, unchanged: 256 thr, warp tile
// 32x32, M128 x N64, double-buffered, paired-tap half2 gather).
// Per buffer (24KB): A@0 16K | B@16K 8K
// ---------------------------------------------------------------------------
#define SM_BUF   24576
#define SM_AHOF  0
#define SM_BHOF  16384
#define SM_TOTAL (2 * SM_BUF)

__global__ __launch_bounds__(256, 2) void deform_kernel(
        const __half* __restrict__ xn, const __half* __restrict__ xs,
        const float4* __restrict__ mw, const int* __restrict__ me,
        const __half* __restrict__ wh,
        const float* __restrict__ db, float* __restrict__ out) {
    extern __shared__ char smem[];
    uint32_t sb = smem_to_u32(smem);

    int tid  = threadIdx.x;
    int lane = tid & 31;
    int warp = tid >> 5;
    int b    = blockIdx.x / 72;
    int pix0 = (blockIdx.x % 72) * 128;

    int p     = tid & 127;
    int chalf = tid >> 7;
    uint32_t a_sts = (uint32_t)p * 128;

    int m0 = (warp & 3) * 32;
    int n0 = (warp >> 2) * 32;

    float acc[2][4][4];
#pragma unroll
    for (int i = 0; i < 2; i++)
#pragma unroll
        for (int j = 0; j < 4; j++)
#pragma unroll
            for (int q = 0; q < 4; q++) acc[i][j][q] = 0.f;

    uint32_t a_m  = lane & 15;
    uint32_t a_kc = lane >> 4;
    uint32_t b_n  = ((lane >> 4) << 3) + (lane & 7);
    uint32_t b_kc = (lane >> 3) & 1;

    int bcp0 = tid;

    auto build_q = [&](int ch, int q, __half2 wtop, __half2 wbot,
                       const __half2* srcp) {
        char* bufc = smem + (ch & 1) * SM_BUF;
        __half v[8];
#pragma unroll
        for (int j = 0; j < 8; j++) {
            const __half2* pl = srcp + (q * 8 + j) * (HW / 2);
            __half2 a  = __ldg(pl);
            __half2 bb = __ldg(pl + (Ww / 2));
            __half2 t  = __hfma2(wbot, bb, __hmul2(wtop, a));
            v[j] = __hadd(__low2half(t), __high2half(t));
        }
        uint32_t hp[4];
#pragma unroll
        for (int jj = 0; jj < 4; jj++) {
            __half2 hb = __halves2half2(v[2 * jj], v[2 * jj + 1]);
            hp[jj] = *(uint32_t*)&hb;
        }
        int kc = chalf * 4 + q;
        uint32_t off = a_sts + (uint32_t)((kc ^ (p & 7)) << 4);
        *(uint4*)(bufc + SM_AHOF + off) = make_uint4(hp[0], hp[1], hp[2], hp[3]);
    };

    auto chunk_meta = [&](int ch, __half2& wtop, __half2& wbot,
                          const __half2*& srcp) {
        int k   = ch / 3;
        int cbl = ch - 3 * k;
        float4 w = __ldg(mw + (b * 9 + k) * HW + pix0 + p);
        int   e0 = __ldg(me + (b * 9 + k) * HW + pix0 + p);
        wtop = __floats2half2_rn(w.x, w.y);
        wbot = __floats2half2_rn(w.z, w.w);
        int sel = e0 & 1;
        int h2base = (e0 - sel) >> 1;
        const __half* base = sel ? xs : xn;
        srcp = (const __half2*)base
             + (size_t)(b * CIN3 + cbl * 64 + chalf * 32) * (HW / 2)
             + h2base;
    };

    auto stage_B = [&](int ch) {
        uint32_t bufb = sb + (ch & 1) * SM_BUF;
        const char* gh = (const char*)(wh + ch * 4096);
        cp_async16(bufb + SM_BHOF + bcp0 * 16, gh + bcp0 * 16);
        cp_async16(bufb + SM_BHOF + (bcp0 + 256) * 16, gh + (bcp0 + 256) * 16);
        CP_COMMIT();
    };

    // prologue: chunk 0
    stage_B(0);
    {
        __half2 wtop, wbot; const __half2* srcp;
        chunk_meta(0, wtop, wbot, srcp);
#pragma unroll
        for (int q = 0; q < 4; q++) build_q(0, q, wtop, wbot, srcp);
    }
    CP_WAIT0();
    __syncthreads();

    for (int ch = 0; ch < NCH; ch++) {
        int nxt = ch + 1;
        bool has_nxt = (nxt < NCH);
        if (has_nxt) stage_B(nxt);

        __half2 nwt = __float2half2_rn(0.f), nwb = __float2half2_rn(0.f);
        const __half2* nsrc = (const __half2*)xn;
        if (has_nxt) chunk_meta(nxt, nwt, nwb, nsrc);

        uint32_t bufb = sb + (ch & 1) * SM_BUF;
#pragma unroll
        for (int ks = 0; ks < 4; ks++) {
            uint32_t ah[2][4], bh[2][4];
#pragma unroll
            for (int mi_ = 0; mi_ < 2; mi_++) {
                uint32_t row = m0 + mi_ * 16 + a_m;
                uint32_t aoff = row * 128 + ((((ks << 1) + a_kc) ^ (row & 7)) << 4);
                ldsm_x4(ah[mi_], bufb + SM_AHOF + aoff);
            }
#pragma unroll
            for (int g = 0; g < 2; g++) {
                uint32_t n  = n0 + g * 16 + b_n;
                uint32_t kc = (ks << 1) + b_kc;
                uint32_t boff = n * 128 + ((kc ^ (n & 7)) << 4);
                ldsm_x4(bh[g], bufb + SM_BHOF + boff);
            }
#pragma unroll
            for (int mi_ = 0; mi_ < 2; mi_++)
#pragma unroll
                for (int g = 0; g < 2; g++)
#pragma unroll
                    for (int s2 = 0; s2 < 2; s2++) {
                        int ni = g * 2 + s2;
                        mma_f16(acc[mi_][ni], ah[mi_], bh[g][2 * s2], bh[g][2 * s2 + 1]);
                    }
            if (has_nxt) build_q(nxt, ks, nwt, nwb, nsrc);
        }

        CP_WAIT0();
        __syncthreads();
    }

    // epilogue: bias + relu
    int r  = lane >> 2;
    int cp = (lane & 3) * 2;
#pragma unroll
    for (int mi_ = 0; mi_ < 2; mi_++) {
        int pixb = pix0 + m0 + mi_ * 16 + r;
#pragma unroll
        for (int ni = 0; ni < 4; ni++) {
            int o = n0 + ni * 8 + cp;
            float b0v = __ldg(db + o);
            float b1v = __ldg(db + o + 1);
            float* o0 = out + (size_t)(b * Oo + o) * HW;
            float* o1 = out + (size_t)(b * Oo + o + 1) * HW;
            float v;
            v = acc[mi_][ni][0] + b0v; o0[pixb]     = v > 0.f ? v : 0.f;
            v = acc[mi_][ni][1] + b1v; o1[pixb]     = v > 0.f ? v : 0.f;
            v = acc[mi_][ni][2] + b0v; o0[pixb + 8] = v > 0.f ? v : 0.f;
            v = acc[mi_][ni][3] + b1v; o1[pixb + 8] = v > 0.f ? v : 0.f;
        }
    }
}

// ---------------------------------------------------------------------------
extern "C" void kernel_launch(void* const* d_in, const int* in_sizes, int n_in,
                              void* d_out, int out_size) {
    const float* ref  = (const float*)d_in[0];
    const float* dist = (const float*)d_in[1];
    const float* ow   = (const float*)d_in[2];
    const float* ob   = (const float*)d_in[3];
    const float* dw   = (const float*)d_in[4];
    const float* db   = (const float*)d_in[5];
    float* out = (float*)d_out;
    float* out_feat = out;
    float* out_diff = out + Bb * IMG;

    float4* mw;  cudaGetSymbolAddress((void**)&mw, g_mw);
    int*    me;  cudaGetSymbolAddress((void**)&me, g_me);
    __half* xnr; cudaGetSymbolAddress((void**)&xnr, g_xn_raw);
    __half* xsr; cudaGetSymbolAddress((void**)&xsr, g_xs_raw);
    __half* wh;  cudaGetSymbolAddress((void**)&wh, g_wh);
    __half* xn = xnr + XPAD;
    __half* xs = xsr + XPAD;

    cudaFuncSetAttribute(deform_kernel,
                         cudaFuncAttributeMaxDynamicSharedMemorySize, SM_TOTAL);
    cudaFuncSetAttribute(offset_meta_kernel,
                         cudaFuncAttributeMaxDynamicSharedMemorySize, 55296);

    prep_kernel<<<RPB + 432, 256>>>(ref, dist, dw, out_diff, xn, xs, wh);
    offset_meta_kernel<<<288, 256, 55296>>>(ref, ow, ob, mw, me);
    deform_kernel<<<NPIX / 128, 256, SM_TOTAL>>>(xn, xs, mw, me, wh, db, out_feat);
}